// round 1
// baseline (speedup 1.0000x reference)
#include <cuda_runtime.h>
#include <cstdint>

typedef unsigned long long u64;

// ---------------- device scratch (no allocations allowed) ----------------
__device__ float g_part_edge[160][64];
__device__ float g_part_node[160][64];
__device__ float g_zhist[64];
__device__ float g_base[64];
__device__ float g_av[64];
__device__ float g_bv[64];
__device__ float g_w2v[64];

// ---------------- f32x2 packed helpers (sm_100 FFMA2 path) ----------------
__device__ __forceinline__ u64 pk2(float a, float b) {
    u64 r; asm("mov.b64 %0,{%1,%2};" : "=l"(r) : "f"(a), "f"(b)); return r;
}
__device__ __forceinline__ void up2(u64 v, float& a, float& b) {
    asm("mov.b64 {%0,%1},%2;" : "=f"(a), "=f"(b) : "l"(v));
}
__device__ __forceinline__ u64 f2fma(u64 a, u64 b, u64 c) {
    u64 d; asm("fma.rn.f32x2 %0,%1,%2,%3;" : "=l"(d) : "l"(a), "l"(b), "l"(c)); return d;
}
__device__ __forceinline__ float tanh_ap(float x) {
    float r; asm("tanh.approx.f32 %0,%1;" : "=f"(r) : "f"(x)); return r;
}
__device__ __forceinline__ float sigm(float x) { return 1.f / (1.f + __expf(-x)); }

// ---------------- staged MLP mean-pool reduction -------------------------
// Thread layout: group of 8 threads (tid&7 selects 8-output j-subset) shares
// 2 rows per iteration; f32x2 lanes = (rowA, rowB). W broadcast-packed in regs.
template<int INF, int RPS>
__device__ __forceinline__ void phase(const float* __restrict__ X,
                                      const float* __restrict__ W,
                                      const float* __restrict__ bias,
                                      int nrows, float* __restrict__ partial,
                                      int nb, int b, float* sh)
{
    const int tid = threadIdx.x;
    const int j0 = (tid & 7) * 8;

    u64 w2[INF * 8];
    u64 b2[8];
#pragma unroll
    for (int k = 0; k < INF; k++)
#pragma unroll
        for (int jj = 0; jj < 8; jj++) {
            float w = W[k * 64 + j0 + jj];
            w2[k * 8 + jj] = pk2(w, w);
        }
#pragma unroll
    for (int jj = 0; jj < 8; jj++) {
        float bb = bias[j0 + jj];
        b2[jj] = pk2(bb, bb);
    }

    u64 acc[8];
#pragma unroll
    for (int jj = 0; jj < 8; jj++) acc[jj] = 0ull;

    const int nstages = (nrows + RPS - 1) / RPS;
    for (int s = b; s < nstages; s += nb) {
        const int r0 = s * RPS;
        const int rows = min(RPS, nrows - r0);
        __syncthreads();
        if (rows == RPS) {
            const float4* src = (const float4*)(X + (size_t)r0 * INF);
            float4* dst = (float4*)sh;
#pragma unroll
            for (int i = tid; i < RPS * INF / 4; i += 256) dst[i] = src[i];
        } else {
            const int nf = rows * INF;
            for (int i = tid; i < RPS * INF; i += 256)
                sh[i] = (i < nf) ? X[(size_t)r0 * INF + i] : 0.f;
        }
        __syncthreads();

#pragma unroll 2
        for (int it = 0; it < RPS / 64; ++it) {
            const int rp = it * 32 + (tid >> 3);
            const int ra = rp * 2, rb = ra + 1;
            const float m0 = (ra < rows) ? 1.f : 0.f;
            const float m1 = (rb < rows) ? 1.f : 0.f;
            const u64 mask = pk2(m0, m1);
            u64 x2[INF];
#pragma unroll
            for (int k = 0; k < INF; k++)
                x2[k] = pk2(sh[ra * INF + k], sh[rb * INF + k]);
#pragma unroll
            for (int jj = 0; jj < 8; jj++) {
                u64 y = b2[jj];
#pragma unroll
                for (int k = 0; k < INF; k++)
                    y = f2fma(x2[k], w2[k * 8 + jj], y);
                float yl, yh; up2(y, yl, yh);
                u64 h = pk2(fmaxf(yl, 0.f), fmaxf(yh, 0.f));
                acc[jj] = f2fma(h, mask, acc[jj]);   // masked accumulate
            }
        }
    }

    // deterministic cross-thread reduce (fixed order; no atomics)
    __syncthreads();
#pragma unroll
    for (int jj = 0; jj < 8; jj++) {
        float a, bb; up2(acc[jj], a, bb);
        sh[tid * 8 + jj] = a + bb;
    }
    __syncthreads();
    if (tid < 64) {
        const int gi = tid >> 3, jj = tid & 7;
        float s = 0.f;
#pragma unroll 4
        for (int g = 0; g < 32; g++) s += sh[(g * 8 + gi) * 8 + jj];
        partial[tid] = s;
    }
    __syncthreads();
}

// ---------------- kernel 1: LSTM (block 0) + node/edge reduce ------------
__global__ void __launch_bounds__(256, 1) k1(
    const float* __restrict__ node, const float* __restrict__ edge,
    const float* __restrict__ hist, int Nn, int Ne, int T,
    const float* __restrict__ nodeW, const float* __restrict__ nodeb,
    const float* __restrict__ edgeW, const float* __restrict__ edgeb,
    const float* __restrict__ Wih, const float* __restrict__ Whh,
    const float* __restrict__ bih, const float* __restrict__ bhh)
{
    __shared__ float sh[5120];
    __shared__ float sh_hist[640];
    __shared__ float sh_g[256];
    __shared__ __align__(8) float sh_h[64];

    const int tid = threadIdx.x;

    if (blockIdx.x == 0) {
        // ---------------- LSTM, 256 threads = one gate row each ----------
        u64 w2[32];
        const float2* wr = (const float2*)(Whh + tid * 64);
#pragma unroll
        for (int k = 0; k < 32; k++) { float2 p = wr[k]; w2[k] = pk2(p.x, p.y); }
        const float wi0 = Wih[tid * 3], wi1 = Wih[tid * 3 + 1], wi2 = Wih[tid * 3 + 2];
        const float bsum = bih[tid] + bhh[tid];

        const bool hsh = (T * 3 <= 640);
        for (int i = tid; i < T * 3 && i < 640; i += 256) sh_hist[i] = hist[i];
        if (tid < 64) sh_h[tid] = 0.f;
        float c = 0.f;
        __syncthreads();

        const bool is_tanh_gate = (tid >= 128 && tid < 192);
        for (int t = 0; t < T; t++) {
            const float* xp = hsh ? (sh_hist + t * 3) : (hist + t * 3);
            float pre = fmaf(wi0, xp[0], fmaf(wi1, xp[1], fmaf(wi2, xp[2], bsum)));
            const u64* hp = (const u64*)sh_h;
            u64 a0 = 0, a1 = 0, a2 = 0, a3 = 0;
#pragma unroll
            for (int k = 0; k < 32; k += 4) {
                a0 = f2fma(w2[k],     hp[k],     a0);
                a1 = f2fma(w2[k + 1], hp[k + 1], a1);
                a2 = f2fma(w2[k + 2], hp[k + 2], a2);
                a3 = f2fma(w2[k + 3], hp[k + 3], a3);
            }
            float s0, s1, s2, s3, s4, s5, s6, s7;
            up2(a0, s0, s1); up2(a1, s2, s3); up2(a2, s4, s5); up2(a3, s6, s7);
            const float z = pre + ((s0 + s1) + (s2 + s3)) + ((s4 + s5) + (s6 + s7));
            sh_g[tid] = is_tanh_gate ? tanh_ap(z) : sigm(z);
            __syncthreads();
            if (tid < 64) {
                const float ig = sh_g[tid], fg = sh_g[64 + tid];
                const float gg = sh_g[128 + tid], og = sh_g[192 + tid];
                c = fmaf(fg, c, ig * gg);
                sh_h[tid] = og * tanh_ap(c);
            }
            __syncthreads();
        }
        if (tid < 64) g_zhist[tid] = sh_h[tid];
    } else {
        const int b = blockIdx.x - 1;
        const int nb = gridDim.x - 1;
        phase<2, 2048>(node, nodeW, nodeb, Nn, g_part_node[b], nb, b, sh);
        phase<5, 1024>(edge, edgeW, edgeb, Ne, g_part_edge[b], nb, b, sh);
    }
}

// ---------------- kernel 2: finalize ctx + precompute base/a/b/w2 --------
__global__ void k2(int nb, int Nn, int Ne,
                   const float* __restrict__ W1, const float* __restrict__ b1,
                   const float* __restrict__ W2f)
{
    __shared__ float ctx[192];
    const int tid = threadIdx.x;
    if (tid < 64) {
        float se = 0.f, sn = 0.f;
        for (int b = 0; b < nb; b++) {
            se += g_part_edge[b][tid];
            sn += g_part_node[b][tid];
        }
        ctx[tid]       = sn * (1.f / (float)Nn);
        ctx[64 + tid]  = se * (1.f / (float)Ne);
        ctx[128 + tid] = g_zhist[tid];
    }
    __syncthreads();
    if (tid < 64) {
        float base = b1[tid];
#pragma unroll 8
        for (int i = 0; i < 192; i++) base = fmaf(ctx[i], W1[i * 64 + tid], base);
        g_base[tid] = base;
        g_av[tid]   = W1[192 * 64 + tid];
        g_bv[tid]   = W1[193 * 64 + tid];
        g_w2v[tid]  = W2f[tid];
    }
}

// ---------------- kernel 3: candidate scoring ----------------------------
__global__ void __launch_bounds__(256) k3(const int* __restrict__ cand, int P,
                                          const int* __restrict__ Np,
                                          const float* __restrict__ fb2,
                                          float* __restrict__ out)
{
    __shared__ __align__(16) u64 s4[128];   // 32 j-pairs x {base2,a2,b2,w22}
    const int tid = threadIdx.x;
    if (tid < 32) {
        s4[tid * 4 + 0] = pk2(g_base[2 * tid], g_base[2 * tid + 1]);
        s4[tid * 4 + 1] = pk2(g_av[2 * tid],   g_av[2 * tid + 1]);
        s4[tid * 4 + 2] = pk2(g_bv[2 * tid],   g_bv[2 * tid + 1]);
        s4[tid * 4 + 3] = pk2(g_w2v[2 * tid],  g_w2v[2 * tid + 1]);
    }
    const float invd = 1.f / ((float)(*Np) - 1.f + 1e-9f);
    const float bias2 = fb2[0];
    __syncthreads();

    int p = blockIdx.x * 1024 + tid;
#pragma unroll
    for (int i = 0; i < 4; i++, p += 256) {
        if (p < P) {
            const int2 cp = ((const int2*)cand)[p];
            const float cx = (float)cp.x * invd;
            const float cy = (float)cp.y * invd;
            const u64 cx2 = pk2(cx, cx), cy2 = pk2(cy, cy);
            u64 acc0 = 0, acc1 = 0;
#pragma unroll
            for (int jp = 0; jp < 32; jp += 2) {
                {
                    u64 tt = f2fma(cx2, s4[jp * 4 + 1], s4[jp * 4 + 0]);
                    tt = f2fma(cy2, s4[jp * 4 + 2], tt);
                    float l, h; up2(tt, l, h);
                    u64 hh = pk2(fmaxf(l, 0.f), fmaxf(h, 0.f));
                    acc0 = f2fma(hh, s4[jp * 4 + 3], acc0);
                }
                {
                    u64 tt = f2fma(cx2, s4[(jp + 1) * 4 + 1], s4[(jp + 1) * 4 + 0]);
                    tt = f2fma(cy2, s4[(jp + 1) * 4 + 2], tt);
                    float l, h; up2(tt, l, h);
                    u64 hh = pk2(fmaxf(l, 0.f), fmaxf(h, 0.f));
                    acc1 = f2fma(hh, s4[(jp + 1) * 4 + 3], acc1);
                }
            }
            float r0, r1, r2, r3;
            up2(acc0, r0, r1); up2(acc1, r2, r3);
            out[p] = (r0 + r1) + (r2 + r3) + bias2;
        }
    }
}

// ---------------- launch --------------------------------------------------
extern "C" void kernel_launch(void* const* d_in, const int* in_sizes, int n_in,
                              void* d_out, int out_size)
{
    const float* node  = (const float*)d_in[0];
    const float* edge  = (const float*)d_in[1];
    const float* hist  = (const float*)d_in[2];
    const int*   cand  = (const int*)d_in[3];
    const int*   Np    = (const int*)d_in[4];
    const float* nodeW = (const float*)d_in[5];
    const float* nodeb = (const float*)d_in[6];
    const float* edgeW = (const float*)d_in[7];
    const float* edgeb = (const float*)d_in[8];
    const float* Wih   = (const float*)d_in[9];
    const float* Whh   = (const float*)d_in[10];
    const float* bih   = (const float*)d_in[11];
    const float* bhh   = (const float*)d_in[12];
    const float* fW1   = (const float*)d_in[13];
    const float* fb1   = (const float*)d_in[14];
    const float* fW2   = (const float*)d_in[15];
    const float* fb2   = (const float*)d_in[16];

    const int Nn = in_sizes[0] / 2;
    const int Ne = in_sizes[1] / 5;
    const int T  = in_sizes[2] / 3;
    const int P  = in_sizes[3] / 2;

    const int GRID1 = 148;  // block 0 = LSTM, 147 = node/edge reduce
    k1<<<GRID1, 256>>>(node, edge, hist, Nn, Ne, T,
                       nodeW, nodeb, edgeW, edgeb, Wih, Whh, bih, bhh);
    k2<<<1, 64>>>(GRID1 - 1, Nn, Ne, fW1, fb1, fW2);
    const int g3 = (P + 1023) / 1024;
    k3<<<g3, 256>>>(cand, P, Np, fb2, (float*)d_out);
}

// round 2
// speedup vs baseline: 1.1293x; 1.1293x over previous
#include <cuda_runtime.h>
#include <cstdint>

typedef unsigned long long u64;

// ---------------- device scratch (no allocations allowed) ----------------
__device__ float g_part_edge[160][64];
__device__ float g_part_node[160][64];
__device__ float g_zhist[64];
__device__ float g_base[64];
__device__ float g_av[64];
__device__ float g_bv[64];
__device__ float g_w2v[64];

// ---------------- f32x2 packed helpers ------------------------------------
__device__ __forceinline__ u64 pk2(float a, float b) {
    u64 r; asm("mov.b64 %0,{%1,%2};" : "=l"(r) : "f"(a), "f"(b)); return r;
}
__device__ __forceinline__ void up2(u64 v, float& a, float& b) {
    asm("mov.b64 {%0,%1},%2;" : "=f"(a), "=f"(b) : "l"(v));
}
__device__ __forceinline__ u64 f2fma(u64 a, u64 b, u64 c) {
    u64 d; asm("fma.rn.f32x2 %0,%1,%2,%3;" : "=l"(d) : "l"(a), "l"(b), "l"(c)); return d;
}
__device__ __forceinline__ u64 add2(u64 a, u64 b) {
    u64 d; asm("add.rn.f32x2 %0,%1,%2;" : "=l"(d) : "l"(a), "l"(b)); return d;
}
// packed relu via paired-register max (movs resolved to register aliasing)
__device__ __forceinline__ u64 relu2(u64 v) {
    u64 r;
    asm("{\n\t.reg .f32 l,h;\n\t"
        "mov.b64 {l,h}, %1;\n\t"
        "max.f32 l, l, 0f00000000;\n\t"
        "max.f32 h, h, 0f00000000;\n\t"
        "mov.b64 %0, {l,h};\n\t}"
        : "=l"(r) : "l"(v));
    return r;
}
__device__ __forceinline__ float tanh_ap(float x) {
    float r; asm("tanh.approx.f32 %0,%1;" : "=f"(r) : "f"(x)); return r;
}
__device__ __forceinline__ float sigm(float x) { return 1.f / (1.f + __expf(-x)); }

// ---------------- staged MLP mean-pool reduction --------------------------
// 512 threads. group of 16 threads (tid&15) -> 4 outputs each (64 total).
// lanes of f32x2 = (rowA, rowB). Shared is TRANSPOSED: sht[k][row] so the
// lane pair is one natural LDS.64 (no packing movs).
#define RPS   1024
#define KPAD  1032

template<int INF>
__device__ __forceinline__ void phase(const float* __restrict__ X,
                                      const float* __restrict__ W,
                                      const float* __restrict__ bias,
                                      int nrows, float* __restrict__ partial,
                                      int nb, int b,
                                      float* __restrict__ sht,  // INF*KPAD floats
                                      float* __restrict__ red)  // 2048 floats
{
    const int tid = threadIdx.x;
    const int j0 = (tid & 15) * 4;
    const int rpb = tid >> 4;          // 0..31

    u64 w2[INF * 4];
    u64 b2[4];
#pragma unroll
    for (int k = 0; k < INF; k++)
#pragma unroll
        for (int jj = 0; jj < 4; jj++) {
            float w = W[k * 64 + j0 + jj];
            w2[k * 4 + jj] = pk2(w, w);
        }
#pragma unroll
    for (int jj = 0; jj < 4; jj++) {
        float bb = bias[j0 + jj];
        b2[jj] = pk2(bb, bb);
    }

    u64 acc[4] = {0ull, 0ull, 0ull, 0ull};

    const int nstages = (nrows + RPS - 1) >> 10;
    float rg[2][INF];

    // prefetch first stage
    if (b < nstages) {
        const int r0 = b << 10;
#pragma unroll
        for (int t2 = 0; t2 < 2; t2++) {
            const int gr = r0 + tid + t2 * 512;
            if (gr < nrows) {
#pragma unroll
                for (int k = 0; k < INF; k++) rg[t2][k] = X[gr * INF + k];
            } else {
#pragma unroll
                for (int k = 0; k < INF; k++) rg[t2][k] = 0.f;
            }
        }
    }

    for (int s = b; s < nstages; s += nb) {
        __syncthreads();
#pragma unroll
        for (int t2 = 0; t2 < 2; t2++) {
            const int j = tid + t2 * 512;
#pragma unroll
            for (int k = 0; k < INF; k++) sht[k * KPAD + j] = rg[t2][k];
        }
        __syncthreads();

        // prefetch next stage (overlaps compute)
        const int sn = s + nb;
        if (sn < nstages) {
            const int r0 = sn << 10;
#pragma unroll
            for (int t2 = 0; t2 < 2; t2++) {
                const int gr = r0 + tid + t2 * 512;
                if (gr < nrows) {
#pragma unroll
                    for (int k = 0; k < INF; k++) rg[t2][k] = X[gr * INF + k];
                } else {
#pragma unroll
                    for (int k = 0; k < INF; k++) rg[t2][k] = 0.f;
                }
            }
        }

        const int rows = min(RPS, nrows - (s << 10));
        if (rows == RPS) {
#pragma unroll 4
            for (int it = 0; it < RPS / 64; ++it) {
                const int rp = it * 32 + rpb;
                u64 x2[INF];
#pragma unroll
                for (int k = 0; k < INF; k++)
                    x2[k] = ((const u64*)(sht + k * KPAD))[rp];
#pragma unroll
                for (int jj = 0; jj < 4; jj++) {
                    u64 y = b2[jj];
#pragma unroll
                    for (int k = 0; k < INF; k++)
                        y = f2fma(x2[k], w2[k * 4 + jj], y);
                    acc[jj] = add2(relu2(y), acc[jj]);
                }
            }
        } else {
#pragma unroll 4
            for (int it = 0; it < RPS / 64; ++it) {
                const int rp = it * 32 + rpb;
                const float m0 = (2 * rp < rows) ? 1.f : 0.f;
                const float m1 = (2 * rp + 1 < rows) ? 1.f : 0.f;
                const u64 mask = pk2(m0, m1);
                u64 x2[INF];
#pragma unroll
                for (int k = 0; k < INF; k++)
                    x2[k] = ((const u64*)(sht + k * KPAD))[rp];
#pragma unroll
                for (int jj = 0; jj < 4; jj++) {
                    u64 y = b2[jj];
#pragma unroll
                    for (int k = 0; k < INF; k++)
                        y = f2fma(x2[k], w2[k * 4 + jj], y);
                    acc[jj] = f2fma(relu2(y), mask, acc[jj]);
                }
            }
        }
    }

    // deterministic cross-thread reduce
    __syncthreads();
    {
        float4 v;
        float a, bb;
        up2(acc[0], a, bb); v.x = a + bb;
        up2(acc[1], a, bb); v.y = a + bb;
        up2(acc[2], a, bb); v.z = a + bb;
        up2(acc[3], a, bb); v.w = a + bb;
        ((float4*)red)[tid] = v;
    }
    __syncthreads();
    if (tid < 64) {
        float s = 0.f;
#pragma unroll 8
        for (int rp = 0; rp < 32; rp++) s += red[rp * 64 + tid];
        partial[tid] = s;
    }
    __syncthreads();
}

// ---------------- kernel 1: LSTM (block 0) + node/edge reduce -------------
__global__ void __launch_bounds__(512, 1) k1(
    const float* __restrict__ node, const float* __restrict__ edge,
    const float* __restrict__ hist, int Nn, int Ne, int T,
    const float* __restrict__ nodeW, const float* __restrict__ nodeb,
    const float* __restrict__ edgeW, const float* __restrict__ edgeb,
    const float* __restrict__ Wih, const float* __restrict__ Whh,
    const float* __restrict__ bih, const float* __restrict__ bhh)
{
    __shared__ __align__(16) float sht[5 * KPAD];
    __shared__ __align__(16) float red[2048];
    __shared__ float sh_hist[608];
    __shared__ float sh_g[256];
    __shared__ __align__(8) float sh_h[64];

    const int tid = threadIdx.x;

    if (blockIdx.x == 0) {
        // ---------------- LSTM: 256 gate threads (of 512) -----------------
        u64 w2[32];
        float wi0 = 0.f, wi1 = 0.f, wi2 = 0.f, bsum = 0.f;
        if (tid < 256) {
            const float2* wr = (const float2*)(Whh + tid * 64);
#pragma unroll
            for (int k = 0; k < 32; k++) { float2 p = wr[k]; w2[k] = pk2(p.x, p.y); }
            wi0 = Wih[tid * 3]; wi1 = Wih[tid * 3 + 1]; wi2 = Wih[tid * 3 + 2];
            bsum = bih[tid] + bhh[tid];
        }
        const bool hsh = (T * 3 <= 608);
        for (int i = tid; i < T * 3 && i < 608; i += 512) sh_hist[i] = hist[i];
        if (tid < 64) sh_h[tid] = 0.f;
        float c = 0.f;
        __syncthreads();

        const bool is_tanh_gate = (tid >= 128 && tid < 192);
        for (int t = 0; t < T; t++) {
            if (tid < 256) {
                const float* xp = hsh ? (sh_hist + t * 3) : (hist + t * 3);
                float pre = fmaf(wi0, xp[0], fmaf(wi1, xp[1], fmaf(wi2, xp[2], bsum)));
                const u64* hp = (const u64*)sh_h;
                u64 a0 = 0, a1 = 0, a2 = 0, a3 = 0;
#pragma unroll
                for (int k = 0; k < 32; k += 4) {
                    a0 = f2fma(w2[k],     hp[k],     a0);
                    a1 = f2fma(w2[k + 1], hp[k + 1], a1);
                    a2 = f2fma(w2[k + 2], hp[k + 2], a2);
                    a3 = f2fma(w2[k + 3], hp[k + 3], a3);
                }
                float s0, s1, s2, s3, s4, s5, s6, s7;
                up2(a0, s0, s1); up2(a1, s2, s3); up2(a2, s4, s5); up2(a3, s6, s7);
                const float z = pre + ((s0 + s1) + (s2 + s3)) + ((s4 + s5) + (s6 + s7));
                sh_g[tid] = is_tanh_gate ? tanh_ap(z) : sigm(z);
            }
            __syncthreads();
            if (tid < 64) {
                const float ig = sh_g[tid], fg = sh_g[64 + tid];
                const float gg = sh_g[128 + tid], og = sh_g[192 + tid];
                c = fmaf(fg, c, ig * gg);
                sh_h[tid] = og * tanh_ap(c);
            }
            __syncthreads();
        }
        if (tid < 64) g_zhist[tid] = sh_h[tid];
    } else {
        const int b = blockIdx.x - 1;
        const int nb = gridDim.x - 1;
        phase<2>(node, nodeW, nodeb, Nn, g_part_node[b], nb, b, sht, red);
        phase<5>(edge, edgeW, edgeb, Ne, g_part_edge[b], nb, b, sht, red);
    }
}

// ---------------- kernel 2: finalize ctx + precompute base/a/b/w2 ---------
__global__ void __launch_bounds__(256) k2(int nb, int Nn, int Ne,
                   const float* __restrict__ W1, const float* __restrict__ b1,
                   const float* __restrict__ W2f)
{
    __shared__ float ctx[192];
    __shared__ float t1[256], t2[256];
    const int tid = threadIdx.x;
    const int c = tid >> 6, j = tid & 63;

    float se = 0.f, sn = 0.f;
    for (int b = c; b < nb; b += 4) {
        se += g_part_edge[b][j];
        sn += g_part_node[b][j];
    }
    t1[tid] = se; t2[tid] = sn;
    __syncthreads();
    if (tid < 64) {
        const float e = t1[tid] + t1[tid + 64] + t1[tid + 128] + t1[tid + 192];
        const float n = t2[tid] + t2[tid + 64] + t2[tid + 128] + t2[tid + 192];
        ctx[tid]       = n * (1.f / (float)Nn);
        ctx[64 + tid]  = e * (1.f / (float)Ne);
        ctx[128 + tid] = g_zhist[tid];
    }
    __syncthreads();
    // base[j] = b1[j] + sum_i ctx[i]*W1[i][j], i split 4 ways
    float p = 0.f;
    const int i0 = c * 48;
#pragma unroll 8
    for (int i = i0; i < i0 + 48; i++) p = fmaf(ctx[i], W1[i * 64 + j], p);
    __syncthreads();
    t1[tid] = p;
    __syncthreads();
    if (tid < 64) {
        g_base[tid] = b1[tid] + ((t1[tid] + t1[tid + 64]) + (t1[tid + 128] + t1[tid + 192]));
        g_av[tid]   = W1[192 * 64 + tid];
        g_bv[tid]   = W1[193 * 64 + tid];
        g_w2v[tid]  = W2f[tid];
    }
}

// ---------------- kernel 3: candidate scoring (ILP=8, shared wt reuse) ----
__global__ void __launch_bounds__(256) k3(const int* __restrict__ cand, int P,
                                          const int* __restrict__ Np,
                                          const float* __restrict__ fb2,
                                          float* __restrict__ out)
{
    __shared__ __align__(16) u64 s4[128];   // [jp]{base2, a2, b2, w22}
    const int tid = threadIdx.x;
    if (tid < 32) {
        s4[tid * 4 + 0] = pk2(g_base[2 * tid], g_base[2 * tid + 1]);
        s4[tid * 4 + 1] = pk2(g_av[2 * tid],   g_av[2 * tid + 1]);
        s4[tid * 4 + 2] = pk2(g_bv[2 * tid],   g_bv[2 * tid + 1]);
        s4[tid * 4 + 3] = pk2(g_w2v[2 * tid],  g_w2v[2 * tid + 1]);
    }
    const float invd = 1.f / ((float)(*Np) - 1.f + 1e-9f);
    const float bias2 = fb2[0];
    __syncthreads();

    const int p0 = blockIdx.x * 2048 + tid;
    u64 cx2[8], cy2[8];
#pragma unroll
    for (int i = 0; i < 8; i++) {
        const int p = p0 + i * 256;
        float cx = 0.f, cy = 0.f;
        if (p < P) {
            const int2 cp = ((const int2*)cand)[p];
            cx = (float)cp.x * invd;
            cy = (float)cp.y * invd;
        }
        cx2[i] = pk2(cx, cx);
        cy2[i] = pk2(cy, cy);
    }

    u64 acc[8] = {0, 0, 0, 0, 0, 0, 0, 0};
#pragma unroll 8
    for (int jp = 0; jp < 32; jp++) {
        const u64 bb = s4[jp * 4 + 0];
        const u64 aa = s4[jp * 4 + 1];
        const u64 bv = s4[jp * 4 + 2];
        const u64 ww = s4[jp * 4 + 3];
#pragma unroll
        for (int i = 0; i < 8; i++) {
            u64 tt = f2fma(cx2[i], aa, bb);
            tt = f2fma(cy2[i], bv, tt);
            acc[i] = f2fma(relu2(tt), ww, acc[i]);
        }
    }
#pragma unroll
    for (int i = 0; i < 8; i++) {
        const int p = p0 + i * 256;
        if (p < P) {
            float l, h; up2(acc[i], l, h);
            out[p] = l + h + bias2;
        }
    }
}

// ---------------- launch ---------------------------------------------------
extern "C" void kernel_launch(void* const* d_in, const int* in_sizes, int n_in,
                              void* d_out, int out_size)
{
    const float* node  = (const float*)d_in[0];
    const float* edge  = (const float*)d_in[1];
    const float* hist  = (const float*)d_in[2];
    const int*   cand  = (const int*)d_in[3];
    const int*   Np    = (const int*)d_in[4];
    const float* nodeW = (const float*)d_in[5];
    const float* nodeb = (const float*)d_in[6];
    const float* edgeW = (const float*)d_in[7];
    const float* edgeb = (const float*)d_in[8];
    const float* Wih   = (const float*)d_in[9];
    const float* Whh   = (const float*)d_in[10];
    const float* bih   = (const float*)d_in[11];
    const float* bhh   = (const float*)d_in[12];
    const float* fW1   = (const float*)d_in[13];
    const float* fb1   = (const float*)d_in[14];
    const float* fW2   = (const float*)d_in[15];
    const float* fb2   = (const float*)d_in[16];

    const int Nn = in_sizes[0] / 2;
    const int Ne = in_sizes[1] / 5;
    const int T  = in_sizes[2] / 3;
    const int P  = in_sizes[3] / 2;

    const int GRID1 = 148;  // block 0 = LSTM, 147 = node/edge reduce
    k1<<<GRID1, 512>>>(node, edge, hist, Nn, Ne, T,
                       nodeW, nodeb, edgeW, edgeb, Wih, Whh, bih, bhh);
    k2<<<1, 256>>>(GRID1 - 1, Nn, Ne, fW1, fb1, fW2);
    const int g3 = (P + 2047) / 2048;
    k3<<<g3, 256>>>(cand, P, Np, fb2, (float*)d_out);
}